// round 2
// baseline (speedup 1.0000x reference)
#include <cuda_runtime.h>
#include <cuda_bf16.h>

#define LOOK_SHORT 21
#define LOOK_LONG  63
#define NFEAT      16
#define ROW_STRIDE (LOOK_LONG * NFEAT)       // 1008 floats per batch row
#define ROW_F4     (ROW_STRIDE / 4)          // 252 float4 per row
#define NOUT       21
#define ROWS_PER_BLOCK 8
#define THREADS    256
#define TOT_F4     (ROWS_PER_BLOCK * ROW_F4) // 2016 float4 per block

__device__ __forceinline__ float warp_sum(float v) {
#pragma unroll
    for (int o = 16; o > 0; o >>= 1) v += __shfl_xor_sync(0xffffffffu, v, o);
    return v;
}
__device__ __forceinline__ float warp_max(float v) {
#pragma unroll
    for (int o = 16; o > 0; o >>= 1) v = fmaxf(v, __shfl_xor_sync(0xffffffffu, v, o));
    return v;
}
__device__ __forceinline__ float warp_min(float v) {
#pragma unroll
    for (int o = 16; o > 0; o >>= 1) v = fminf(v, __shfl_xor_sync(0xffffffffu, v, o));
    return v;
}

__global__ __launch_bounds__(THREADS)
void regime_feature_kernel(const float4* __restrict__ x4,
                           float* __restrict__ out,
                           int B) {
    const int tid  = threadIdx.x;
    const int lane = tid & 31;
    const int wrp  = tid >> 5;              // warp id == row within block
    const int row0 = blockIdx.x * ROWS_PER_BLOCK;

    __shared__ float s_r[ROWS_PER_BLOCK][LOOK_LONG + 1];
    __shared__ float s_vf[ROWS_PER_BLOCK][LOOK_SHORT + 3];
    __shared__ float s_rsi[ROWS_PER_BLOCK];
    __shared__ float s_mom[ROWS_PER_BLOCK];

    // ---------------- Phase 1: fully coalesced float4 load ----------------
    const float4* __restrict__ base = x4 + (size_t)row0 * ROW_F4;
#pragma unroll
    for (int it = 0; it < 8; ++it) {
        int i = tid + it * THREADS;          // 0..2047, need < 2016
        if (it < 7 || i < TOT_F4) {
            float4 v = base[i];
            int rrow = i / ROW_F4;           // 0..7
            int q    = i - rrow * ROW_F4;    // 0..251
            int t    = q >> 2;               // timestep 0..62
            int part = q & 3;                // which 4-col group
            if (part == 0) {
                s_r[rrow][t] = v.x;          // col 0 = r
                if (t == 62) s_rsi[rrow] = v.y;   // col 1 at last t
            } else if (part == 2) {
                if (t >= 42) s_vf[rrow][t - 42] = v.z;  // col 10, last 21 t
            } else if (part == 3) {
                if (t == 62) s_mom[rrow] = v.w;         // col 15 at last t
            }
        }
    }
    __syncthreads();

    // ---------------- Phase 2: one warp per row ----------------
    const int row = row0 + wrp;
    if (row >= B) return;
    const float* r = s_r[wrp];

    float r0 = r[lane];
    const bool has2 = (lane < 31);
    float r1 = has2 ? r[lane + 32] : 0.0f;
    float vf = (lane < LOOK_SHORT) ? s_vf[wrp][lane] : 0.0f;

    // pass-1 reductions
    float sum    = warp_sum(r0 + r1);
    float sumsq  = warp_sum(r0 * r0 + r1 * r1);
    float sumabs = warp_sum(fabsf(r0) + fabsf(r1));
    // short window: t in [42,62] -> r1 of lanes 10..30
    float sv = (has2 && lane >= 10) ? r1 : 0.0f;
    float ssum   = warp_sum(sv);
    float ssumsq = warp_sum(sv * sv);
    // lag-1 cross product
    float ab = r0 * r[lane + 1];
    if (lane <= 29) ab += r1 * r[lane + 33];
    float sum_ab = warp_sum(ab);
    float vf_sum = warp_sum(vf);
    float rmax = warp_max(has2 ? fmaxf(r0, r1) : r0);
    float rmin = warp_min(has2 ? fminf(r0, r1) : r0);

    const float n  = 63.0f;
    float mean     = sum / n;
    float var_long = fmaxf(0.0f, (sumsq - sum * sum / n)) / 62.0f;
    float vol_long = sqrtf(var_long);
    float var_s    = fmaxf(0.0f, (ssumsq - ssum * ssum / 21.0f)) / 20.0f;
    float vol_short = sqrtf(var_s);
    float vol_ratio = vol_short / (vol_long + 1e-8f);
    float high_vol = (vol_short > 0.03f) ? 1.0f : 0.0f;
    float med_vol  = ((vol_short >= 0.01f) && (vol_short <= 0.03f)) ? 1.0f : 0.0f;
    float low_vol  = (vol_short < 0.01f) ? 1.0f : 0.0f;

    float rfirst = r[0], rlast = r[62];
    float sa  = sum - rlast;
    float sb  = sum - rfirst;
    float saa = sumsq - rlast * rlast;
    float sbb = sumsq - rfirst * rfirst;
    float cnum = sum_ab - sa * sb / 62.0f;
    float cden = sqrtf((saa - sa * sa / 62.0f) * (sbb - sb * sb / 62.0f));
    float corr = cnum / cden;
    float trend_strength = (corr != corr) ? 0.5f : fabsf(corr);

    // skewness (centered cubes)
    float d1 = r0 - mean;
    float d2 = has2 ? (r1 - mean) : 0.0f;
    float sum_c3 = warp_sum(d1 * d1 * d1 + d2 * d2 * d2);
    float skewness = 0.0f;
    if (vol_long >= 1e-8f) {
        float inv_s3 = 1.0f / (vol_long * vol_long * vol_long);
        skewness = (sum_c3 / n) * inv_s3;
    }

    float momentum_short   = rlast / (r[42] + 1e-8f) - 1.0f;
    float return_range     = rmax - rmin;
    float vol_feature_mean = vf_sum / 21.0f;

    // sliding-window stds: j = 62,57,...,22 (9 windows, 22 elems, ddof=1)
    float vs_l = 0.0f;
    if (lane < 9) {
        int j = 62 - 5 * lane;
        float ws = 0.0f, wss = 0.0f;
#pragma unroll
        for (int k = 0; k < 22; ++k) {
            float v = r[j - 21 + k];
            ws += v;
            wss += v * v;
        }
        vs_l = sqrtf(fmaxf(0.0f, (wss - ws * ws / 22.0f)) / 21.0f);
    }
    float vs_sum  = warp_sum(vs_l);
    float vs_sum2 = warp_sum(vs_l * vs_l);
    float m_vs = vs_sum / 9.0f;
    float vol_persistence = sqrtf(fmaxf(0.0f, vs_sum2 / 9.0f - m_vs * m_vs));
    float vs_first = __shfl_sync(0xffffffffu, vs_l, 0);
    float vs_last  = __shfl_sync(0xffffffffu, vs_l, 8);
    float vol_trend = vs_first - vs_last;

    // write 21 features, coalesced across lanes 0..20
    float fv = 0.0f;
    switch (lane) {
        case 0:  fv = high_vol; break;
        case 1:  fv = med_vol; break;
        case 2:  fv = low_vol; break;
        case 3:  fv = trend_strength; break;
        case 4:  fv = vol_ratio; break;
        case 5:  fv = mean; break;
        case 6:  fv = sumabs / n; break;
        case 7:  fv = return_range; break;
        case 8:  fv = skewness; break;
        case 9:  fv = momentum_short; break;
        case 10: fv = s_rsi[wrp]; break;
        case 11: fv = vol_feature_mean; break;
        case 12: fv = s_mom[wrp]; break;
        case 13: fv = 0.0f; break;
        case 14: fv = 1.0f; break;
        case 15: fv = 1.0f; break;
        case 16: fv = 0.0f; break;
        case 17: fv = 0.02f; break;
        case 18: fv = vol_persistence; break;
        case 19: fv = vol_trend; break;
        case 20: fv = 0.0f; break;
        default: break;
    }
    if (lane < NOUT) out[(size_t)row * NOUT + lane] = fv;
}

extern "C" void kernel_launch(void* const* d_in, const int* in_sizes, int n_in,
                              void* d_out, int out_size) {
    const float4* x4 = (const float4*)d_in[0];
    float* out = (float*)d_out;
    int B = in_sizes[0] / ROW_STRIDE;
    int blocks = (B + ROWS_PER_BLOCK - 1) / ROWS_PER_BLOCK;
    regime_feature_kernel<<<blocks, THREADS>>>(x4, out, B);
}

// round 3
// speedup vs baseline: 1.4406x; 1.4406x over previous
#include <cuda_runtime.h>
#include <cuda_bf16.h>

#define LOOK_SHORT 21
#define LOOK_LONG  63
#define NFEAT      16
#define ROW_STRIDE (LOOK_LONG * NFEAT)       // 1008 floats per batch row
#define ROW_F4     (ROW_STRIDE / 4)          // 252 float4 per row
#define NOUT       21
#define WARPS_PER_BLOCK 8
#define THREADS    (WARPS_PER_BLOCK * 32)

__device__ __forceinline__ float warp_sum(float v) {
#pragma unroll
    for (int o = 16; o > 0; o >>= 1) v += __shfl_xor_sync(0xffffffffu, v, o);
    return v;
}
__device__ __forceinline__ float warp_max(float v) {
#pragma unroll
    for (int o = 16; o > 0; o >>= 1) v = fmaxf(v, __shfl_xor_sync(0xffffffffu, v, o));
    return v;
}
__device__ __forceinline__ float warp_min(float v) {
#pragma unroll
    for (int o = 16; o > 0; o >>= 1) v = fminf(v, __shfl_xor_sync(0xffffffffu, v, o));
    return v;
}

__global__ __launch_bounds__(THREADS)
void regime_feature_kernel(const float4* __restrict__ x4,
                           float* __restrict__ out,
                           int B) {
    const int lane = threadIdx.x & 31;
    const int wrp  = threadIdx.x >> 5;
    const int row  = blockIdx.x * WARPS_PER_BLOCK + wrp;
    if (row >= B) return;

    __shared__ float s_r[WARPS_PER_BLOCK][LOOK_LONG + 1];
    __shared__ float s_vf[WARPS_PER_BLOCK][LOOK_SHORT + 3];
    __shared__ float s_rsi[WARPS_PER_BLOCK];
    __shared__ float s_mom[WARPS_PER_BLOCK];

    // ---- Phase 1: warp loads its own row contiguously, branch-free LDG.128 x8 ----
    const float4* __restrict__ base4 = x4 + (size_t)row * ROW_F4;
    float4 v[8];
#pragma unroll
    for (int k = 0; k < 8; ++k) {
        int i = lane + 32 * k;               // 0..255; row has 252
        if (k < 7 || lane < 28)              // only last iter predicated
            v[k] = base4[i];
    }

    // ---- register -> smem scatter of the needed columns ----
    const int part = lane & 3;               // which 4-col group: 0:{0..3} 2:{8..11} 3:{12..15}
    const int tb   = lane >> 2;              // base timestep offset 0..7
#pragma unroll
    for (int k = 0; k < 8; ++k) {
        if (k < 7 || lane < 28) {
            int t = tb + 8 * k;              // timestep 0..62
            if (part == 0) {
                s_r[wrp][t] = v[k].x;        // col 0 = r
                if (t == 62) s_rsi[wrp] = v[k].y;          // col 1, last t
            } else if (part == 2) {
                if (t >= 42) s_vf[wrp][t - 42] = v[k].z;   // col 10, last 21 t
            } else if (part == 3) {
                if (t == 62) s_mom[wrp] = v[k].w;          // col 15, last t
            }
        }
    }
    __syncwarp();

    // ---- Phase 2: per-warp feature computation (identical math to R1) ----
    const float* r = s_r[wrp];
    float r0 = r[lane];
    const bool has2 = (lane < 31);
    float r1 = has2 ? r[lane + 32] : 0.0f;
    float vf = (lane < LOOK_SHORT) ? s_vf[wrp][lane] : 0.0f;

    float sum    = warp_sum(r0 + r1);
    float sumsq  = warp_sum(r0 * r0 + r1 * r1);
    float sumabs = warp_sum(fabsf(r0) + fabsf(r1));
    float sv = (has2 && lane >= 10) ? r1 : 0.0f;       // short window t in [42,62]
    float ssum   = warp_sum(sv);
    float ssumsq = warp_sum(sv * sv);
    float ab = r0 * r[lane + 1];                        // lag-1 cross product
    if (lane <= 29) ab += r1 * r[lane + 33];
    float sum_ab = warp_sum(ab);
    float vf_sum = warp_sum(vf);
    float rmax = warp_max(has2 ? fmaxf(r0, r1) : r0);
    float rmin = warp_min(has2 ? fminf(r0, r1) : r0);

    const float n  = 63.0f;
    float mean     = sum / n;
    float var_long = fmaxf(0.0f, (sumsq - sum * sum / n)) / 62.0f;
    float vol_long = sqrtf(var_long);
    float var_s    = fmaxf(0.0f, (ssumsq - ssum * ssum / 21.0f)) / 20.0f;
    float vol_short = sqrtf(var_s);
    float vol_ratio = vol_short / (vol_long + 1e-8f);
    float high_vol = (vol_short > 0.03f) ? 1.0f : 0.0f;
    float med_vol  = ((vol_short >= 0.01f) && (vol_short <= 0.03f)) ? 1.0f : 0.0f;
    float low_vol  = (vol_short < 0.01f) ? 1.0f : 0.0f;

    float rfirst = r[0], rlast = r[62];
    float sa  = sum - rlast;
    float sb  = sum - rfirst;
    float saa = sumsq - rlast * rlast;
    float sbb = sumsq - rfirst * rfirst;
    float cnum = sum_ab - sa * sb / 62.0f;
    float cden = sqrtf((saa - sa * sa / 62.0f) * (sbb - sb * sb / 62.0f));
    float corr = cnum / cden;
    float trend_strength = (corr != corr) ? 0.5f : fabsf(corr);

    float d1 = r0 - mean;
    float d2 = has2 ? (r1 - mean) : 0.0f;
    float sum_c3 = warp_sum(d1 * d1 * d1 + d2 * d2 * d2);
    float skewness = 0.0f;
    if (vol_long >= 1e-8f) {
        float inv_s3 = 1.0f / (vol_long * vol_long * vol_long);
        skewness = (sum_c3 / n) * inv_s3;
    }

    float momentum_short   = rlast / (r[42] + 1e-8f) - 1.0f;
    float return_range     = rmax - rmin;
    float vol_feature_mean = vf_sum / 21.0f;

    // sliding-window stds: j = 62,57,...,22 (9 windows of 22 elems, ddof=1)
    float vs_l = 0.0f;
    if (lane < 9) {
        int j = 62 - 5 * lane;
        float ws = 0.0f, wss = 0.0f;
#pragma unroll
        for (int k = 0; k < 22; ++k) {
            float vv = r[j - 21 + k];
            ws += vv;
            wss += vv * vv;
        }
        vs_l = sqrtf(fmaxf(0.0f, (wss - ws * ws / 22.0f)) / 21.0f);
    }
    float vs_sum  = warp_sum(vs_l);
    float vs_sum2 = warp_sum(vs_l * vs_l);
    float m_vs = vs_sum / 9.0f;
    float vol_persistence = sqrtf(fmaxf(0.0f, vs_sum2 / 9.0f - m_vs * m_vs));
    float vs_first = __shfl_sync(0xffffffffu, vs_l, 0);
    float vs_last  = __shfl_sync(0xffffffffu, vs_l, 8);
    float vol_trend = vs_first - vs_last;

    // write 21 features, coalesced across lanes 0..20
    float fv = 0.0f;
    switch (lane) {
        case 0:  fv = high_vol; break;
        case 1:  fv = med_vol; break;
        case 2:  fv = low_vol; break;
        case 3:  fv = trend_strength; break;
        case 4:  fv = vol_ratio; break;
        case 5:  fv = mean; break;
        case 6:  fv = sumabs / n; break;
        case 7:  fv = return_range; break;
        case 8:  fv = skewness; break;
        case 9:  fv = momentum_short; break;
        case 10: fv = s_rsi[wrp]; break;
        case 11: fv = vol_feature_mean; break;
        case 12: fv = s_mom[wrp]; break;
        case 13: fv = 0.0f; break;
        case 14: fv = 1.0f; break;
        case 15: fv = 1.0f; break;
        case 16: fv = 0.0f; break;
        case 17: fv = 0.02f; break;
        case 18: fv = vol_persistence; break;
        case 19: fv = vol_trend; break;
        case 20: fv = 0.0f; break;
        default: break;
    }
    if (lane < NOUT) out[(size_t)row * NOUT + lane] = fv;
}

extern "C" void kernel_launch(void* const* d_in, const int* in_sizes, int n_in,
                              void* d_out, int out_size) {
    const float4* x4 = (const float4*)d_in[0];
    float* out = (float*)d_out;
    int B = in_sizes[0] / ROW_STRIDE;
    int blocks = (B + WARPS_PER_BLOCK - 1) / WARPS_PER_BLOCK;
    regime_feature_kernel<<<blocks, THREADS>>>(x4, out, B);
}

// round 4
// speedup vs baseline: 2.0460x; 1.4202x over previous
#include <cuda_runtime.h>
#include <cuda_bf16.h>
#include <math_constants.h>

#define LOOK_LONG  63
#define NFEAT      16
#define ROW_STRIDE (LOOK_LONG * NFEAT)   // 1008 floats per batch row
#define NOUT       21
#define ROWS_PER_WARP 4
#define WARPS_PER_BLOCK 8
#define THREADS    (WARPS_PER_BLOCK * 32)
#define ROWS_PER_BLOCK (WARPS_PER_BLOCK * ROWS_PER_WARP)   // 32
#define SSTRIDE    72                    // smem floats per row (bank-conflict-free)

__device__ __forceinline__ float grp_sum(float v) {
    v += __shfl_xor_sync(0xffffffffu, v, 4);
    v += __shfl_xor_sync(0xffffffffu, v, 2);
    v += __shfl_xor_sync(0xffffffffu, v, 1);
    return v;
}
__device__ __forceinline__ float grp_max(float v) {
    v = fmaxf(v, __shfl_xor_sync(0xffffffffu, v, 4));
    v = fmaxf(v, __shfl_xor_sync(0xffffffffu, v, 2));
    v = fmaxf(v, __shfl_xor_sync(0xffffffffu, v, 1));
    return v;
}
__device__ __forceinline__ float grp_min(float v) {
    v = fminf(v, __shfl_xor_sync(0xffffffffu, v, 4));
    v = fminf(v, __shfl_xor_sync(0xffffffffu, v, 2));
    v = fminf(v, __shfl_xor_sync(0xffffffffu, v, 1));
    return v;
}

__global__ __launch_bounds__(THREADS)
void regime_feature_kernel(const float* __restrict__ x,
                           float* __restrict__ out,
                           int B) {
    const int lane = threadIdx.x & 31;
    const int wrp  = threadIdx.x >> 5;
    const int s    = lane >> 3;          // sub-row 0..3
    const int i    = lane & 7;           // lane within sub-row
    const int row  = blockIdx.x * ROWS_PER_BLOCK + wrp * ROWS_PER_WARP + s;
    const int row_c = (row < B) ? row : (B - 1);

    __shared__ float s_r[WARPS_PER_BLOCK][ROWS_PER_WARP * SSTRIDE];
    float* sr = s_r[wrp] + s * SSTRIDE;

    const float* __restrict__ xr = x + (size_t)row_c * ROW_STRIDE;

    // ---- front-batched loads: 8 r values (t = i + 8k), vf, rsi, mom ----
    float xv[8];
#pragma unroll
    for (int k = 0; k < 8; ++k) {
        const int t = i + 8 * k;
        if (k < 7) xv[k] = xr[t * NFEAT];
        else       xv[k] = (i < 7) ? xr[t * NFEAT] : 0.0f;   // t=63 -> 0
    }
    float vfacc = xr[(42 + i) * NFEAT + 10] + xr[(50 + i) * NFEAT + 10];
    if (i < 5) vfacc += xr[(58 + i) * NFEAT + 10];
    const float rsi  = xr[62 * NFEAT + 1];
    const float momc = xr[62 * NFEAT + 15];

    // ---- stage r into smem (slot 63 gets 0 from the invalid lane) ----
#pragma unroll
    for (int k = 0; k < 8; ++k) sr[i + 8 * k] = xv[k];
    __syncwarp();

    // ---- serial pass over 8 owned values ----
    float sum = 0.f, ssq = 0.f, sr3 = 0.f, sab = 0.f, shs = 0.f, shq = 0.f;
    float mx = -CUDART_INF_F, mn = CUDART_INF_F;
#pragma unroll
    for (int k = 0; k < 8; ++k) {
        const float xx = xv[k];
        const float x2 = xx * xx;
        sum += xx;
        ssq += x2;
        sr3 = fmaf(x2, xx, sr3);
        sab += fabsf(xx);
        if (k == 5) { const bool p = (i >= 2); shs += p ? xx : 0.f; shq += p ? x2 : 0.f; }
        if (k >= 6) { shs += xx; shq += x2; }               // t>=48 always in short window
        if (k == 7) { const bool v7 = (i < 7);
                      mx = v7 ? fmaxf(mx, xx) : mx;
                      mn = v7 ? fminf(mn, xx) : mn; }
        else        { mx = fmaxf(mx, xx); mn = fminf(mn, xx); }
    }

    // ---- lag-1 products: t in 0..61 contribute; t=62 hits sr[63]=0, t=63 clamped ----
    float abacc = 0.f;
#pragma unroll
    for (int k = 0; k < 8; ++k) {
        int idx = i + 8 * k + 1;
        if (k == 7) idx = (idx > 63) ? 63 : idx;            // i=7 -> sr[63]=0
        abacc = fmaf(xv[k], sr[idx], abacc);
    }

    // ---- 3-step subgroup reductions (each instruction serves 4 rows) ----
    sum   = grp_sum(sum);
    ssq   = grp_sum(ssq);
    sr3   = grp_sum(sr3);
    sab   = grp_sum(sab);
    shs   = grp_sum(shs);
    shq   = grp_sum(shq);
    abacc = grp_sum(abacc);
    vfacc = grp_sum(vfacc);
    mx    = grp_max(mx);
    mn    = grp_min(mn);

    // ---- sliding-window stds: windows 0..7 (lane i), window 8 (all lanes) ----
    float ws = 0.f, wq = 0.f;
    const int wbase = 41 - 5 * i;        // j = 62-5i, window = r[j-21 .. j]
#pragma unroll
    for (int k = 0; k < 22; ++k) {
        const float v = sr[wbase + k];
        ws += v;
        wq = fmaf(v, v, wq);
    }
    const float vs_i = sqrtf(fmaxf(0.f, (wq - ws * ws * (1.0f / 22.0f))) * (1.0f / 21.0f));
    float w8s = 0.f, w8q = 0.f;          // window 8: j=22, r[1..22]
#pragma unroll
    for (int k = 0; k < 22; ++k) {
        const float v = sr[1 + k];
        w8s += v;
        w8q = fmaf(v, v, w8q);
    }
    const float vs8 = sqrtf(fmaxf(0.f, (w8q - w8s * w8s * (1.0f / 22.0f))) * (1.0f / 21.0f));

    const float vs_sum  = grp_sum(vs_i) + vs8;
    const float vs_sum2 = grp_sum(vs_i * vs_i) + vs8 * vs8;
    const float m_vs = vs_sum * (1.0f / 9.0f);
    const float vol_persistence = sqrtf(fmaxf(0.f, vs_sum2 * (1.0f / 9.0f) - m_vs * m_vs));
    const float vs0 = __shfl_sync(0xffffffffu, vs_i, lane & ~7);
    const float vol_trend = vs0 - vs8;

    // ---- derived scalars (uniform within each 8-lane subgroup) ----
    const float n = 63.0f;
    const float mean = sum / n;
    const float var_long = fmaxf(0.f, (ssq - sum * sum / n)) * (1.0f / 62.0f);
    const float vol_long = sqrtf(var_long);
    const float var_s = fmaxf(0.f, (shq - shs * shs * (1.0f / 21.0f))) * (1.0f / 20.0f);
    const float vol_short = sqrtf(var_s);
    const float vol_ratio = vol_short / (vol_long + 1e-8f);
    const float high_vol = (vol_short > 0.03f) ? 1.0f : 0.0f;
    const float med_vol  = ((vol_short >= 0.01f) && (vol_short <= 0.03f)) ? 1.0f : 0.0f;
    const float low_vol  = (vol_short < 0.01f) ? 1.0f : 0.0f;

    const float rfirst = sr[0], rlast = sr[62], r42 = sr[42];
    const float sa  = sum - rlast;
    const float sb  = sum - rfirst;
    const float saa = ssq - rlast * rlast;
    const float sbb = ssq - rfirst * rfirst;
    const float cnum = abacc - sa * sb * (1.0f / 62.0f);
    const float cden = sqrtf((saa - sa * sa * (1.0f / 62.0f)) * (sbb - sb * sb * (1.0f / 62.0f)));
    const float corr = cnum / cden;
    const float trend_strength = (corr != corr) ? 0.5f : fabsf(corr);

    // skewness from raw moments: sum(x-mu)^3 = sr3 - 3 mu ssq + 2 mu^2 sum
    float skewness = 0.0f;
    if (vol_long >= 1e-8f) {
        const float c3 = sr3 - 3.0f * mean * ssq + 2.0f * mean * mean * sum;
        skewness = (c3 / n) / (vol_long * vol_long * vol_long);
    }

    const float momentum_short = rlast / (r42 + 1e-8f) - 1.0f;
    const float return_range = mx - mn;
    const float vol_feature_mean = vfacc * (1.0f / 21.0f);
    const float abs_mean = sab / n;

    // ---- each lane writes features i, i+8, i+16 ----
    float a0, a1, a2 = 0.0f;
    switch (i) {
        case 0: a0 = high_vol;  a1 = skewness;        a2 = 0.0f;            break; // f16 rel_strength
        case 1: a0 = med_vol;   a1 = momentum_short;  a2 = 0.02f;           break; // f17 mkt_vol
        case 2: a0 = low_vol;   a1 = rsi;             a2 = vol_persistence; break; // f18
        case 3: a0 = trend_strength; a1 = vol_feature_mean; a2 = vol_trend; break; // f19
        case 4: a0 = vol_ratio; a1 = momc;            a2 = 0.0f;            break; // f20 regime_shift
        case 5: a0 = mean;      a1 = 0.0f;            break;                        // f13 rel_return
        case 6: a0 = abs_mean;  a1 = 1.0f;            break;                        // f14 rel_vol
        default:a0 = return_range; a1 = 1.0f;         break;                        // f15 beta
    }
    if (row < B) {
        float* o = out + (size_t)row * NOUT;
        o[i]     = a0;
        o[i + 8] = a1;
        if (i < 5) o[i + 16] = a2;
    }
}

extern "C" void kernel_launch(void* const* d_in, const int* in_sizes, int n_in,
                              void* d_out, int out_size) {
    const float* x = (const float*)d_in[0];
    float* out = (float*)d_out;
    int B = in_sizes[0] / ROW_STRIDE;
    int blocks = (B + ROWS_PER_BLOCK - 1) / ROWS_PER_BLOCK;
    regime_feature_kernel<<<blocks, THREADS>>>(x, out, B);
}